// round 12
// baseline (speedup 1.0000x reference)
#include <cuda_runtime.h>
#include <math.h>
#include <stdint.h>

// Problem constants
#define BATCH 2
#define NPTS 1024
#define NUM_BINS 22
#define TDIM 16
#define TSTRIDE 20           // padded table row stride (floats); 80B rows, 16B aligned
#define MAX_DIST 40.0f
#define LN_EPS 1e-5f
#define NBLOCKS (4 * 1024 * 2)   // gridDim.x * gridDim.y * gridDim.z

// Table + once-per-launch publication state (reset by the last block each launch).
__device__ float    g_table[NUM_BINS * TSTRIDE];
__device__ unsigned g_flag = 0;   // 1 = table ready
__device__ unsigned g_done = 0;   // finished-block counter

// ---------------------------------------------------------------------------
// Single fused kernel (ONE graph node).
//  Block (0,0,0): threads 0..21 build T[bin]=relu(LN(W[bin]+b)*gamma+beta)
//                 into g_table, then release-publish g_flag.
//  All blocks:    acquire-probe g_flag at entry (latency hidden under PhaseA),
//                 re-spin only if probe saw 0 (wave-1 blocks only).
//  Phase A: per-j (bin byte-offset, scale) -> smem.
//  Phase B: 4 lanes/pair, LDS.64 broadcast + __ldg float4 table gather (L1-hot),
//           2 packed f32x2 muls, STG.128.
//  Epilogue: last finishing block resets g_flag/g_done (replay-safe, no caching).
// ---------------------------------------------------------------------------
__global__ __launch_bounds__(256, 8)
void encode_kernel(const float* __restrict__ coords,
                   const float* __restrict__ conf,
                   const float* __restrict__ W,
                   const float* __restrict__ bb,
                   const float* __restrict__ gamma,
                   const float* __restrict__ beta,
                   float* __restrict__ out) {
    __shared__ float2 sP[256];    // (row byte-offset, scale) per local j

    const int tid    = threadIdx.x;
    const int i      = blockIdx.y;
    const int batch  = blockIdx.z;
    const int j_base = blockIdx.x * 256;
    const bool builder = (blockIdx.x == 0) && (blockIdx.y == 0) && (blockIdx.z == 0);

    // ---- Early acquire-probe (non-builder, lane 0): hidden under Phase A ----
    unsigned probe = 1;
    if (!builder && tid == 0) {
        asm volatile("ld.acquire.gpu.global.u32 %0, [%1];"
                     : "=r"(probe) : "l"(&g_flag) : "memory");
    }

    // ---- Builder: compute table once, publish ----
    if (builder) {
        if (tid < NUM_BINS) {
            float h[TDIM];
            float sum = 0.0f;
#pragma unroll
            for (int d = 0; d < TDIM; ++d) {
                h[d] = W[tid * TDIM + d] + bb[d];
                sum += h[d];
            }
            const float mu = sum * (1.0f / TDIM);
            float var = 0.0f;
#pragma unroll
            for (int d = 0; d < TDIM; ++d) {
                const float c = h[d] - mu;
                var += c * c;
            }
            var *= (1.0f / TDIM);
            const float inv = rsqrtf(var + LN_EPS);
            float o[TDIM];
#pragma unroll
            for (int d = 0; d < TDIM; ++d)
                o[d] = fmaxf((h[d] - mu) * inv * gamma[d] + beta[d], 0.0f);
            float4* row = (float4*)(g_table + tid * TSTRIDE);
            row[0] = make_float4(o[0],  o[1],  o[2],  o[3]);
            row[1] = make_float4(o[4],  o[5],  o[6],  o[7]);
            row[2] = make_float4(o[8],  o[9],  o[10], o[11]);
            row[3] = make_float4(o[12], o[13], o[14], o[15]);
        }
        if (tid < 32) __syncwarp();
        if (tid == 0) {
            __threadfence();
            asm volatile("st.release.gpu.global.u32 [%0], %1;"
                         :: "l"(&g_flag), "r"(1u) : "memory");
        }
    }

    // ---- Phase A: per-j precompute (one thread per j; table-independent) ----
    {
        const float* ci_ptr = coords + ((size_t)batch * NPTS + i) * 3;
        const float xi = ci_ptr[0], yi = ci_ptr[1], zi = ci_ptr[2];
        const float ci = conf[batch * NPTS + i];

        const int j = j_base + tid;
        const float* cj_ptr = coords + ((size_t)batch * NPTS + j) * 3;
        const float dx = xi - cj_ptr[0];
        const float dy = yi - cj_ptr[1];
        const float dz = zi - cj_ptr[2];
        const float cj = conf[batch * NPTS + j];

        const float dist = sqrtf(fmaf(dx, dx, fmaf(dy, dy, fmaf(dz, dz, 1e-8f))));
        const float inv_w = (float)(NUM_BINS - 1) / MAX_DIST;  // 21/40

        int bin;
        if (ci > 0.0f && cj > 0.0f) {
            bin = (int)(dist * inv_w) + 1;          // #edges strictly below dist
            bin = (bin > NUM_BINS - 2) ? (NUM_BINS - 2) : bin;
        } else {
            bin = NUM_BINS - 1;
        }
        sP[tid] = make_float2(__int_as_float(bin * (TSTRIDE * 4)),
                              fminf(ci, cj));
    }

    // ---- Wait for table publication (rarely spins: wave-1 only) ----
    if (!builder && tid == 0 && probe == 0) {
        unsigned f;
        do {
            asm volatile("ld.acquire.gpu.global.u32 %0, [%1];"
                         : "=r"(f) : "l"(&g_flag) : "memory");
        } while (f == 0);
    }
    __syncthreads();   // orders tid0's acquire before all threads' table reads

    // ---- Phase B: table gather + scale + store ----
    const int p = tid >> 2;   // pair slot within 64
    const int k = tid & 3;    // which float4 of the 16-vector

    float* optr = out + (((size_t)batch * NPTS + i) * NPTS + j_base + p) * TDIM + k * 4;
    const char* tbase = (const char*)g_table + k * 16;

#pragma unroll
    for (int it = 0; it < 4; ++it) {
        const float2 pk = sP[it * 64 + p];      // broadcast within 4-lane group
        const int   off = __float_as_int(pk.x);
        const float s   = pk.y;

        const float4 v = __ldg((const float4*)(tbase + off));   // L1-hot

        // packed f32x2 multiplies: 2 instructions instead of 4
        uint64_t lo, hi, sv, rlo, rhi;
        asm("mov.b64 %0, {%1, %2};" : "=l"(sv) : "f"(s), "f"(s));
        asm("mov.b64 %0, {%1, %2};" : "=l"(lo) : "f"(v.x), "f"(v.y));
        asm("mov.b64 %0, {%1, %2};" : "=l"(hi) : "f"(v.z), "f"(v.w));
        asm("mul.rn.f32x2 %0, %1, %2;" : "=l"(rlo) : "l"(lo), "l"(sv));
        asm("mul.rn.f32x2 %0, %1, %2;" : "=l"(rhi) : "l"(hi), "l"(sv));
        float4 r;
        asm("mov.b64 {%0, %1}, %2;" : "=f"(r.x), "=f"(r.y) : "l"(rlo));
        asm("mov.b64 {%0, %1}, %2;" : "=f"(r.z), "=f"(r.w) : "l"(rhi));

        *(float4*)(optr + (size_t)it * 64 * TDIM) = r;
    }

    // ---- Epilogue: last block resets publication state (replay-safe) ----
    if (tid == 0) {
        const unsigned n = atomicAdd(&g_done, 1u);
        if (n == NBLOCKS - 1) {
            g_done = 0;
            __threadfence();
            g_flag = 0;
        }
    }
}

// ---------------------------------------------------------------------------
// Launch: single kernel, single graph node.
// ---------------------------------------------------------------------------
extern "C" void kernel_launch(void* const* d_in, const int* in_sizes, int n_in,
                              void* d_out, int out_size) {
    const float* coords = (const float*)d_in[0];  // (B,N,3)
    const float* conf   = (const float*)d_in[1];  // (B,N)
    const float* W      = (const float*)d_in[2];  // (22,16)
    const float* b      = (const float*)d_in[3];  // (16,)
    const float* gamma  = (const float*)d_in[4];  // (16,)
    const float* beta   = (const float*)d_in[5];  // (16,)
    float* out = (float*)d_out;                   // (B,N,N,16)

    dim3 grid(NPTS / 256, NPTS, BATCH);
    encode_kernel<<<grid, 256>>>(coords, conf, W, b, gamma, beta, out);
}

// round 14
// speedup vs baseline: 1.2376x; 1.2376x over previous
#include <cuda_runtime.h>
#include <math.h>
#include <stdint.h>

// Problem constants
#define BATCH 2
#define NPTS 1024
#define NUM_BINS 22
#define TDIM 16
#define TSTRIDE 20           // padded table row stride (floats) for LDS conflicts
#define MAX_DIST 40.0f
#define LN_EPS 1e-5f

// ---------------------------------------------------------------------------
// Single fused kernel (ONE graph node), fully-parallel in-block table build:
//   Stage 1: each thread issues <=5 coalesced LDG.32 for its (bin,d) table
//            element inputs (w0, w1, b[d], gamma[d], beta[d]) — latency only.
//   Stage 2: Phase A (per-j bin offset + scale -> smem) hides stage-1 latency.
//   Stage 3: LN via 4-step shfl_xor butterfly in 16-lane segments (one thread
//            per (bin,d)); pass 0 = bins 0..15 (all 256 thr), pass 1 =
//            bins 16..21 (threads 0..95 = 3 full warps). ~130-cycle tail.
//   Phase B: R2's proven body: LDS.64 broadcast + LDS.128 table row chunk,
//            2 packed f32x2 muls, STG.128.
// Grid (N/256, N, B) = 8192 blocks of 256.
// ---------------------------------------------------------------------------
__global__ __launch_bounds__(256)
void encode_kernel(const float* __restrict__ coords,
                   const float* __restrict__ conf,
                   const float* __restrict__ W,
                   const float* __restrict__ bb,
                   const float* __restrict__ gamma,
                   const float* __restrict__ beta,
                   float* __restrict__ out) {
    __shared__ float  sT[NUM_BINS * TSTRIDE];
    __shared__ float2 sP[256];    // (row byte-offset, scale) per local j

    const int tid    = threadIdx.x;
    const int i      = blockIdx.y;
    const int batch  = blockIdx.z;
    const int j_base = blockIdx.x * 256;

    // ---- Stage 1: issue table-input loads early (5 regs live, coalesced) ----
    const int d    = tid & 15;        // dim within row
    const int bin0 = tid >> 4;        // 0..15  (pass 0)
    float w0 = W[bin0 * TDIM + d];
    float w1 = 0.0f;
    if (tid < 96) w1 = W[(16 + bin0) * TDIM + d];   // pass 1: bins 16..21
    const float bd = bb[d];
    const float gd = gamma[d];
    const float ed = beta[d];

    // ---- Stage 2: Phase A (all threads; hides stage-1 latency) ----
    {
        const float* ci_ptr = coords + ((size_t)batch * NPTS + i) * 3;
        const float xi = ci_ptr[0], yi = ci_ptr[1], zi = ci_ptr[2];
        const float ci = conf[batch * NPTS + i];

        const int j = j_base + tid;
        const float* cj_ptr = coords + ((size_t)batch * NPTS + j) * 3;
        const float dx = xi - cj_ptr[0];
        const float dy = yi - cj_ptr[1];
        const float dz = zi - cj_ptr[2];
        const float cj = conf[batch * NPTS + j];

        const float dist = sqrtf(fmaf(dx, dx, fmaf(dy, dy, fmaf(dz, dz, 1e-8f))));
        const float inv_w = (float)(NUM_BINS - 1) / MAX_DIST;  // 21/40

        int bin;
        if (ci > 0.0f && cj > 0.0f) {
            bin = (int)(dist * inv_w) + 1;          // #edges strictly below dist
            bin = (bin > NUM_BINS - 2) ? (NUM_BINS - 2) : bin;
        } else {
            bin = NUM_BINS - 1;
        }
        sP[tid] = make_float2(__int_as_float(bin * (TSTRIDE * 4)),
                              fminf(ci, cj));
    }

    // ---- Stage 3: parallel LN (shfl butterfly within 16-lane segments) ----
    {
        // pass 0: bins 0..15
        const float h = w0 + bd;
        float s = h, q = h * h;
#pragma unroll
        for (int m = 1; m < 16; m <<= 1) {
            s += __shfl_xor_sync(0xFFFFFFFFu, s, m);
            q += __shfl_xor_sync(0xFFFFFFFFu, q, m);
        }
        const float mu  = s * (1.0f / TDIM);
        const float var = fmaxf(q * (1.0f / TDIM) - mu * mu, 0.0f);
        const float inv = rsqrtf(var + LN_EPS);
        sT[bin0 * TSTRIDE + d] = fmaxf((h - mu) * inv * gd + ed, 0.0f);
    }
    if (tid < 96) {
        // pass 1: bins 16..21 (3 full warps; no shfl divergence)
        const float h = w1 + bd;
        float s = h, q = h * h;
#pragma unroll
        for (int m = 1; m < 16; m <<= 1) {
            s += __shfl_xor_sync(0xFFFFFFFFu, s, m);
            q += __shfl_xor_sync(0xFFFFFFFFu, q, m);
        }
        const float mu  = s * (1.0f / TDIM);
        const float var = fmaxf(q * (1.0f / TDIM) - mu * mu, 0.0f);
        const float inv = rsqrtf(var + LN_EPS);
        sT[(16 + bin0) * TSTRIDE + d] = fmaxf((h - mu) * inv * gd + ed, 0.0f);
    }
    __syncthreads();

    // ---- Phase B: gather + scale + store ----
    const int p = tid >> 2;   // pair slot within 64
    const int k = tid & 3;    // which float4 of the 16-vector

    float* optr = out + (((size_t)batch * NPTS + i) * NPTS + j_base + p) * TDIM + k * 4;
    const char* tbase = (const char*)sT + k * 16;

#pragma unroll
    for (int it = 0; it < 4; ++it) {
        const float2 pk = sP[it * 64 + p];      // broadcast within 4-lane group
        const int   off = __float_as_int(pk.x);
        const float sc  = pk.y;

        float4 v = *(const float4*)(tbase + off);

        // packed f32x2 multiplies: 2 instructions instead of 4
        uint64_t lo, hi, sv, rlo, rhi;
        asm("mov.b64 %0, {%1, %2};" : "=l"(sv) : "f"(sc), "f"(sc));
        asm("mov.b64 %0, {%1, %2};" : "=l"(lo) : "f"(v.x), "f"(v.y));
        asm("mov.b64 %0, {%1, %2};" : "=l"(hi) : "f"(v.z), "f"(v.w));
        asm("mul.rn.f32x2 %0, %1, %2;" : "=l"(rlo) : "l"(lo), "l"(sv));
        asm("mul.rn.f32x2 %0, %1, %2;" : "=l"(rhi) : "l"(hi), "l"(sv));
        float4 r;
        asm("mov.b64 {%0, %1}, %2;" : "=f"(r.x), "=f"(r.y) : "l"(rlo));
        asm("mov.b64 {%0, %1}, %2;" : "=f"(r.z), "=f"(r.w) : "l"(rhi));

        *(float4*)(optr + (size_t)it * 64 * TDIM) = r;
    }
}

// ---------------------------------------------------------------------------
// Launch: single kernel, single graph node.
// ---------------------------------------------------------------------------
extern "C" void kernel_launch(void* const* d_in, const int* in_sizes, int n_in,
                              void* d_out, int out_size) {
    const float* coords = (const float*)d_in[0];  // (B,N,3)
    const float* conf   = (const float*)d_in[1];  // (B,N)
    const float* W      = (const float*)d_in[2];  // (22,16)
    const float* b      = (const float*)d_in[3];  // (16,)
    const float* gamma  = (const float*)d_in[4];  // (16,)
    const float* beta   = (const float*)d_in[5];  // (16,)
    float* out = (float*)d_out;                   // (B,N,N,16)

    dim3 grid(NPTS / 256, NPTS, BATCH);
    encode_kernel<<<grid, 256>>>(coords, conf, W, b, gamma, beta, out);
}